// round 2
// baseline (speedup 1.0000x reference)
#include <cuda_runtime.h>
#include <math.h>

#define MAX_IN 64
#define D_MODEL 64
#define ROWS_PER_BLOCK 16
#define THREADS 256   // 16 groups of 16 threads; each group handles one row

__device__ __forceinline__ float fast_tanh(float x) {
    float y;
    asm("tanh.approx.f32 %0, %1;" : "=f"(y) : "f"(x));
    return y;
}

__device__ __forceinline__ float gelu_tanh(float v) {
    const float c = 0.7978845608028654f;
    float u = c * (v + 0.044715f * v * v * v);
    return 0.5f * v * (1.0f + fast_tanh(u));
}

__global__ __launch_bounds__(THREADS)
void fe_kernel(const float* __restrict__ seg,
               const float* __restrict__ W,
               const float* __restrict__ b,
               const int*   __restrict__ lengths,
               float* __restrict__ out,
               int n)
{
    __shared__ float sx[ROWS_PER_BLOCK][MAX_IN];
    __shared__ int   slen[ROWS_PER_BLOCK];

    const int row0 = blockIdx.x * ROWS_PER_BLOCK;
    const int tid  = threadIdx.x;

    if (tid < ROWS_PER_BLOCK) {
        int r = row0 + tid;
        slen[tid] = (r < n) ? lengths[r] : 0;
    }
    __syncthreads();

    // Cooperative masked load of x rows into smem: 16 rows * 16 float4
    {
        int r  = tid >> 4;
        int c4 = tid & 15;
        int row = row0 + r;
        float4 v = make_float4(0.f, 0.f, 0.f, 0.f);
        if (row < n) {
            v = reinterpret_cast<const float4*>(seg)[(size_t)row * 16 + c4];
            int len = slen[r];
            int c = c4 * 4;
            if (c + 0 >= len) v.x = 0.f;
            if (c + 1 >= len) v.y = 0.f;
            if (c + 2 >= len) v.z = 0.f;
            if (c + 3 >= len) v.w = 0.f;
        }
        *reinterpret_cast<float4*>(&sx[r][c4 * 4]) = v;
    }
    __syncthreads();

    const int g = tid >> 4;       // row within block
    const int t = tid & 15;       // d-chunk (4 cols via float4)
    const int row = row0 + g;
    if (row >= n) return;

    const int len = slen[g];
    const float4* Wr = reinterpret_cast<const float4*>(W) + (size_t)row * 1024 + t;
    const float* xr = sx[g];

    float4 acc = make_float4(0.f, 0.f, 0.f, 0.f);

    int i = 0;
    const int len8 = len & ~7;
    // Unroll x8: 8 independent LDG.128 in flight before first consume
    for (; i < len8; i += 8) {
        float4 w0 = Wr[(i + 0) * 16];
        float4 w1 = Wr[(i + 1) * 16];
        float4 w2 = Wr[(i + 2) * 16];
        float4 w3 = Wr[(i + 3) * 16];
        float4 w4 = Wr[(i + 4) * 16];
        float4 w5 = Wr[(i + 5) * 16];
        float4 w6 = Wr[(i + 6) * 16];
        float4 w7 = Wr[(i + 7) * 16];
        float x0 = xr[i + 0], x1 = xr[i + 1], x2 = xr[i + 2], x3 = xr[i + 3];
        float x4 = xr[i + 4], x5 = xr[i + 5], x6 = xr[i + 6], x7 = xr[i + 7];
        acc.x += x0 * w0.x + x1 * w1.x + x2 * w2.x + x3 * w3.x
               + x4 * w4.x + x5 * w5.x + x6 * w6.x + x7 * w7.x;
        acc.y += x0 * w0.y + x1 * w1.y + x2 * w2.y + x3 * w3.y
               + x4 * w4.y + x5 * w5.y + x6 * w6.y + x7 * w7.y;
        acc.z += x0 * w0.z + x1 * w1.z + x2 * w2.z + x3 * w3.z
               + x4 * w4.z + x5 * w5.z + x6 * w6.z + x7 * w7.z;
        acc.w += x0 * w0.w + x1 * w1.w + x2 * w2.w + x3 * w3.w
               + x4 * w4.w + x5 * w5.w + x6 * w6.w + x7 * w7.w;
    }
    if (i + 4 <= len) {
        float4 w0 = Wr[(i + 0) * 16];
        float4 w1 = Wr[(i + 1) * 16];
        float4 w2 = Wr[(i + 2) * 16];
        float4 w3 = Wr[(i + 3) * 16];
        float x0 = xr[i + 0], x1 = xr[i + 1], x2 = xr[i + 2], x3 = xr[i + 3];
        acc.x += x0 * w0.x + x1 * w1.x + x2 * w2.x + x3 * w3.x;
        acc.y += x0 * w0.y + x1 * w1.y + x2 * w2.y + x3 * w3.y;
        acc.z += x0 * w0.z + x1 * w1.z + x2 * w2.z + x3 * w3.z;
        acc.w += x0 * w0.w + x1 * w1.w + x2 * w2.w + x3 * w3.w;
        i += 4;
    }
    for (; i < len; i++) {
        float4 w = Wr[i * 16];
        float xv = xr[i];
        acc.x += xv * w.x;
        acc.y += xv * w.y;
        acc.z += xv * w.z;
        acc.w += xv * w.w;
    }

    float4 bb = reinterpret_cast<const float4*>(b)[(size_t)row * 16 + t];
    float4 r4;
    r4.x = gelu_tanh(acc.x + bb.x);
    r4.y = gelu_tanh(acc.y + bb.y);
    r4.z = gelu_tanh(acc.z + bb.z);
    r4.w = gelu_tanh(acc.w + bb.w);

    reinterpret_cast<float4*>(out)[(size_t)row * 16 + t] = r4;
}

extern "C" void kernel_launch(void* const* d_in, const int* in_sizes, int n_in,
                              void* d_out, int out_size) {
    const float* seg     = (const float*)d_in[0];
    const float* W       = (const float*)d_in[1];
    const float* b       = (const float*)d_in[2];
    const int*   lengths = (const int*)d_in[3];
    float* out = (float*)d_out;

    int n = in_sizes[3];

    int grid = (n + ROWS_PER_BLOCK - 1) / ROWS_PER_BLOCK;
    fe_kernel<<<grid, THREADS>>>(seg, W, b, lengths, out, n);
}

// round 3
// speedup vs baseline: 1.2877x; 1.2877x over previous
#include <cuda_runtime.h>
#include <math.h>

#define MAX_IN 64
#define D_MODEL 64
#define ROWS_PER_BLOCK 16
#define THREADS 256   // 16 groups of 16 threads; each group handles one row

__device__ __forceinline__ float fast_tanh(float x) {
    float y;
    asm("tanh.approx.f32 %0, %1;" : "=f"(y) : "f"(x));
    return y;
}

__device__ __forceinline__ float gelu_tanh(float v) {
    const float c = 0.7978845608028654f;
    float u = c * (v + 0.044715f * v * v * v);
    return 0.5f * v * (1.0f + fast_tanh(u));
}

__global__ __launch_bounds__(THREADS, 6)
void fe_kernel(const float* __restrict__ seg,
               const float* __restrict__ W,
               const float* __restrict__ b,
               const int*   __restrict__ lengths,
               float* __restrict__ out,
               int n)
{
    __shared__ float sx[ROWS_PER_BLOCK][MAX_IN];
    __shared__ int   slen[ROWS_PER_BLOCK];

    const int row0 = blockIdx.x * ROWS_PER_BLOCK;
    const int tid  = threadIdx.x;

    if (tid < ROWS_PER_BLOCK) {
        int r = row0 + tid;
        slen[tid] = (r < n) ? lengths[r] : 0;
    }
    __syncthreads();

    // Cooperative masked load of x rows into smem: 16 rows * 16 float4
    {
        int r  = tid >> 4;
        int c4 = tid & 15;
        int row = row0 + r;
        float4 v = make_float4(0.f, 0.f, 0.f, 0.f);
        if (row < n) {
            v = reinterpret_cast<const float4*>(seg)[(size_t)row * 16 + c4];
            int len = slen[r];
            int c = c4 * 4;
            if (c + 0 >= len) v.x = 0.f;
            if (c + 1 >= len) v.y = 0.f;
            if (c + 2 >= len) v.z = 0.f;
            if (c + 3 >= len) v.w = 0.f;
        }
        *reinterpret_cast<float4*>(&sx[r][c4 * 4]) = v;
    }
    __syncthreads();

    const int g = tid >> 4;       // row within block
    const int t = tid & 15;       // d-chunk (4 cols via float4)
    const int row = row0 + g;
    if (row >= n) return;

    // Round trip count up to a multiple of 4: x is zero-padded in smem,
    // so the extra terms contribute 0 — no scalar tail needed.
    const int len4 = (slen[g] + 3) & ~3;
    const float4* Wr = reinterpret_cast<const float4*>(W) + (size_t)row * 1024 + t;
    const float* xr = sx[g];

    float4 acc = make_float4(0.f, 0.f, 0.f, 0.f);

    #pragma unroll 1
    for (int i = 0; i < len4; i += 4) {
        float4 w0 = Wr[(i + 0) * 16];
        float4 w1 = Wr[(i + 1) * 16];
        float4 w2 = Wr[(i + 2) * 16];
        float4 w3 = Wr[(i + 3) * 16];
        float4 xv = *reinterpret_cast<const float4*>(xr + i);  // one LDS.128
        acc.x += xv.x * w0.x + xv.y * w1.x + xv.z * w2.x + xv.w * w3.x;
        acc.y += xv.x * w0.y + xv.y * w1.y + xv.z * w2.y + xv.w * w3.y;
        acc.z += xv.x * w0.z + xv.y * w1.z + xv.z * w2.z + xv.w * w3.z;
        acc.w += xv.x * w0.w + xv.y * w1.w + xv.z * w2.w + xv.w * w3.w;
    }

    float4 bb = reinterpret_cast<const float4*>(b)[(size_t)row * 16 + t];
    float4 r4;
    r4.x = gelu_tanh(acc.x + bb.x);
    r4.y = gelu_tanh(acc.y + bb.y);
    r4.z = gelu_tanh(acc.z + bb.z);
    r4.w = gelu_tanh(acc.w + bb.w);

    reinterpret_cast<float4*>(out)[(size_t)row * 16 + t] = r4;
}

extern "C" void kernel_launch(void* const* d_in, const int* in_sizes, int n_in,
                              void* d_out, int out_size) {
    const float* seg     = (const float*)d_in[0];
    const float* W       = (const float*)d_in[1];
    const float* b       = (const float*)d_in[2];
    const int*   lengths = (const int*)d_in[3];
    float* out = (float*)d_out;

    int n = in_sizes[3];

    int grid = (n + ROWS_PER_BLOCK - 1) / ROWS_PER_BLOCK;
    fe_kernel<<<grid, THREADS>>>(seg, W, b, lengths, out, n);
}